// round 5
// baseline (speedup 1.0000x reference)
#include <cuda_runtime.h>
#include <stdint.h>

#define NPTS 8192
#define MAXE (64 * NPTS)
#define WPR  (NPTS / 32)   // 256 mask words per row

// Static scratch (no allocations allowed)
__device__ float4 g_pos4[NPTS];
__device__ __align__(16) unsigned g_mask[NPTS * WPR];   // 8 MB bitmask
__device__ int g_cnt[NPTS];
__device__ int g_off[NPTS + 1];

// ---------------------------------------------------------------------------
// Pass A: pack (x, y, z, sq) — full fp32.
// sq replicates jnp.sum(pos*pos,-1): ((x^2 + y^2) + z^2), separate rn ops.
// ---------------------------------------------------------------------------
__global__ void pack_kernel(const float* __restrict__ pos) {
    int i = blockIdx.x * blockDim.x + threadIdx.x;
    if (i < NPTS) {
        float x = pos[3 * i + 0];
        float y = pos[3 * i + 1];
        float z = pos[3 * i + 2];
        float sq = __fadd_rn(__fadd_rn(__fmul_rn(x, x), __fmul_rn(y, y)),
                             __fmul_rn(z, z));
        g_pos4[i] = make_float4(x, y, z, sq);
    }
}

// ---------------------------------------------------------------------------
// Pass B: mask + count. One warp per row; ballot per 32-col chunk.
// Full-fp32 gemm model (Blackwell: TF32 deprecated; cuBLAS/XLA fp32 or bf16x9
// emulation == fp32-accurate). K=3 ascending-k fma chain:
//     dot = fma(z,z', fma(y,y', rn(x*x')))
// Epilogue: d2 = rn((sq_i + sq_j) - 2*dot)   (2*dot exact -> single rounding)
// mask <=> sqrt_rn(max(d2,0)) < 5 <=> d2 < pred(25) = 0x41C7FFFF.
// ---------------------------------------------------------------------------
__global__ void mask_kernel() {
    int gwarp = (blockIdx.x * blockDim.x + threadIdx.x) >> 5;
    int lane  = threadIdx.x & 31;
    if (gwarp >= NPTS) return;
    const int i = gwarp;
    const float4 pi = g_pos4[i];
    const float T = __uint_as_float(0x41C7FFFFu);  // pred(25.0f)

    int cnt = 0;
    unsigned* mrow = g_mask + (size_t)i * WPR;
#pragma unroll 4
    for (int c = 0; c < WPR; ++c) {
        int j = c * 32 + lane;
        float4 pj = g_pos4[j];
        float dot = __fmaf_rn(pi.z, pj.z,
                    __fmaf_rn(pi.y, pj.y,
                    __fmul_rn(pi.x, pj.x)));
        float s  = __fadd_rn(pi.w, pj.w);
        float d2 = __fmaf_rn(-2.0f, dot, s);
        bool m = (d2 < T) && (j != i);
        unsigned b = __ballot_sync(0xffffffffu, m);
        if (lane == 0) mrow[c] = b;
        cnt += __popc(b);
    }
    if (lane == 0) g_cnt[i] = cnt;
}

// ---------------------------------------------------------------------------
// Pass C: exclusive scan of 8192 row counts, single block of 1024 threads.
// ---------------------------------------------------------------------------
__global__ void scan_kernel() {
    __shared__ int warp_sums[32];
    int tid  = threadIdx.x;          // 1024 threads
    int lane = tid & 31;
    int wid  = tid >> 5;

    int base = tid * 8;
    int v[8];
    int s = 0;
#pragma unroll
    for (int k = 0; k < 8; ++k) { v[k] = g_cnt[base + k]; s += v[k]; }

    int x = s;
#pragma unroll
    for (int d = 1; d < 32; d <<= 1) {
        int y = __shfl_up_sync(0xffffffffu, x, d);
        if (lane >= d) x += y;
    }
    if (lane == 31) warp_sums[wid] = x;
    __syncthreads();
    if (wid == 0) {
        int w = warp_sums[lane];
        int xx = w;
#pragma unroll
        for (int d = 1; d < 32; d <<= 1) {
            int y = __shfl_up_sync(0xffffffffu, xx, d);
            if (lane >= d) xx += y;
        }
        warp_sums[lane] = xx;
    }
    __syncthreads();

    int warp_excl = (wid == 0) ? 0 : warp_sums[wid - 1];
    int run = warp_excl + (x - s);   // exclusive prefix for this thread
#pragma unroll
    for (int k = 0; k < 8; ++k) { g_off[base + k] = run; run += v[k]; }
    if (tid == 1023) g_off[NPTS] = run;
}

// ---------------------------------------------------------------------------
// Pass D: emit as FLOAT32 values. One warp per row; lane L owns mask words
// [8L, 8L+8) i.e. cols [256L, 256L+256) -> row-major order preserved.
// ---------------------------------------------------------------------------
__global__ void emit_kernel(float* __restrict__ out) {
    int gwarp = (blockIdx.x * blockDim.x + threadIdx.x) >> 5;
    int lane  = threadIdx.x & 31;
    if (gwarp >= NPTS) return;
    const int i = gwarp;

    const uint4* mrow = (const uint4*)(g_mask + (size_t)i * WPR);
    uint4 a = mrow[lane * 2 + 0];
    uint4 b = mrow[lane * 2 + 1];
    unsigned w[8] = {a.x, a.y, a.z, a.w, b.x, b.y, b.z, b.w};

    int pc = 0;
#pragma unroll
    for (int k = 0; k < 8; ++k) pc += __popc(w[k]);

    int x = pc;
#pragma unroll
    for (int d = 1; d < 32; d <<= 1) {
        int y = __shfl_up_sync(0xffffffffu, x, d);
        if (lane >= d) x += y;
    }
    int off = g_off[i] + (x - pc);

    float fi = (float)i;
    int colbase = lane * 256;
#pragma unroll
    for (int k = 0; k < 8; ++k) {
        unsigned ww = w[k];
        int cb = colbase + k * 32;
        while (ww) {
            int bit = __ffs(ww) - 1;
            out[off]        = fi;                  // rows plane
            out[MAXE + off] = (float)(cb + bit);   // cols plane
            ++off;
            ww &= ww - 1;
        }
    }
}

// ---------------------------------------------------------------------------
// Pass E: fill padding with -1.0f (output poisoned; must write the tail).
// ---------------------------------------------------------------------------
__global__ void fill_kernel(float* __restrict__ out) {
    int e = blockIdx.x * blockDim.x + threadIdx.x;
    if (e < MAXE) {
        int total = g_off[NPTS];
        if (e >= total) {
            out[e]        = -1.0f;
            out[MAXE + e] = -1.0f;
        }
    }
}

extern "C" void kernel_launch(void* const* d_in, const int* in_sizes, int n_in,
                              void* d_out, int out_size) {
    const float* pos = (const float*)d_in[0];
    float* out = (float*)d_out;

    pack_kernel<<<(NPTS + 255) / 256, 256>>>(pos);
    mask_kernel<<<NPTS / 8, 256>>>();          // 8 warps (rows) per block
    scan_kernel<<<1, 1024>>>();
    emit_kernel<<<NPTS / 8, 256>>>(out);
    fill_kernel<<<(MAXE + 255) / 256, 256>>>(out);
}